// round 5
// baseline (speedup 1.0000x reference)
#include <cuda_runtime.h>
#include <cuda_fp16.h>

#define NN 100000
#define NE 1600000
#define NG 1024
#define SCAN_B 1024

// ---------------- scratch (static __device__ — no allocation allowed) ----------
__device__ int    g_cnt[NN];        // incoming-edge count per node (excl. self loop)
__device__ int    g_off[NN];        // CSR exclusive offsets
__device__ int    g_fill[NN];       // bucket cursors
__device__ float  g_dinv[NN];       // 1/sqrt(deg) (deg incl. self loop)
__device__ int    g_bsum[128];      // per-tile scan partials
__device__ int    g_srcs[NE];       // CSR src ids (sorted by dst)
__device__ float  g_xs[NN * 4];     // dinv-prescaled input features
__device__ __half g_y1h[NN * 64];   // dinv * relu(a1 @ W1 + b1)  (layer-2 pre-scaled)
__device__ float  g_pool[NG * 128]; // graph-pooled sums
__device__ int    g_gcnt[NG];       // nodes per graph
__device__ int    g_is64;           // index dtype flag

// ---------------- index dtype handling -----------------------------------------
__device__ __forceinline__ int ld_idx(const void* p, long long i, int is64) {
    return is64 ? (int)((const long long*)p)[i] : ((const int*)p)[i];
}

__global__ void k_detect(const unsigned int* w) {
    if (threadIdx.x == 0 && blockIdx.x == 0) {
        int is64 = 1;
        #pragma unroll 1
        for (int i = 0; i < 256; i++) {
            if (w[2 * i + 1] != 0u) { is64 = 0; break; }
        }
        g_is64 = is64;
    }
}

// ---------------- init ----------------------------------------------------------
__global__ void k_zero() {
    int i = blockIdx.x * blockDim.x + threadIdx.x;
    if (i < NN) { g_cnt[i] = 0; g_fill[i] = 0; }
    if (i < NG * 128) g_pool[i] = 0.0f;
    if (i < NG) g_gcnt[i] = 0;
}

// ---------------- CSR build -----------------------------------------------------
__global__ void k_count(const void* ei, int E) {
    int e = blockIdx.x * blockDim.x + threadIdx.x;
    if (e < E) {
        int is64 = g_is64;
        int d = ld_idx(ei, (long long)E + e, is64);
        atomicAdd(&g_cnt[d], 1);
    }
}

// grid-wide exclusive scan, phase 1: per-tile warp-shuffle scan + tile sums
__global__ void k_scan1(int n) {
    __shared__ int swarp[32];
    int t = threadIdx.x;
    int i = blockIdx.x * SCAN_B + t;
    int lane = t & 31, wid = t >> 5;
    int v = (i < n) ? g_cnt[i] : 0;
    int s = v;
    #pragma unroll
    for (int o = 1; o < 32; o <<= 1) {
        int u = __shfl_up_sync(0xffffffffu, s, o);
        if (lane >= o) s += u;
    }
    if (lane == 31) swarp[wid] = s;
    __syncthreads();
    if (wid == 0) {
        int ws = swarp[lane];
        #pragma unroll
        for (int o = 1; o < 32; o <<= 1) {
            int u = __shfl_up_sync(0xffffffffu, ws, o);
            if (lane >= o) ws += u;
        }
        swarp[lane] = ws;
    }
    __syncthreads();
    int incl = s + (wid > 0 ? swarp[wid - 1] : 0);
    if (i < n) g_off[i] = incl - v;   // exclusive within tile
    if (t == SCAN_B - 1) g_bsum[blockIdx.x] = incl;
}

// phase 2: scan the (<=128) tile sums in one block
__global__ void k_scan2(int nb) {
    __shared__ int sw[4];
    int t = threadIdx.x;       // 128
    int lane = t & 31, wid = t >> 5;
    int v = (t < nb) ? g_bsum[t] : 0;
    int s = v;
    #pragma unroll
    for (int o = 1; o < 32; o <<= 1) {
        int u = __shfl_up_sync(0xffffffffu, s, o);
        if (lane >= o) s += u;
    }
    if (lane == 31) sw[wid] = s;
    __syncthreads();
    int add = 0;
    #pragma unroll
    for (int w = 0; w < 4; w++) if (w < wid) add += sw[w];
    g_bsum[t] = s - v + add;    // exclusive
}

// phase 3: add tile offsets; compute dinv; prescale x by dinv
__global__ void k_scan3(const float* __restrict__ x, int n) {
    int i = blockIdx.x * SCAN_B + threadIdx.x;
    if (i < n) {
        g_off[i] += g_bsum[blockIdx.x];
        float dn = rsqrtf((float)(g_cnt[i] + 1));   // +1 = self loop
        g_dinv[i] = dn;
        float4 xi = ((const float4*)x)[i];
        float4 r; r.x = dn * xi.x; r.y = dn * xi.y; r.z = dn * xi.z; r.w = dn * xi.w;
        ((float4*)g_xs)[i] = r;
    }
}

__global__ void k_fill(const void* ei, int E) {
    int e = blockIdx.x * blockDim.x + threadIdx.x;
    if (e < E) {
        int is64 = g_is64;
        int s = ld_idx(ei, e, is64);
        int d = ld_idx(ei, (long long)E + e, is64);
        int slot = g_off[d] + atomicAdd(&g_fill[d], 1);
        g_srcs[slot] = s;
    }
}

// ---------------- fused layer 1: gather-sum (4-dim) + W1 projection + relu -------
__global__ void k_l1(const float* __restrict__ W1, const float* __restrict__ b1, int n) {
    __shared__ float sW[256];
    __shared__ float sb[64];
    int t = threadIdx.x;  // 128
    sW[t] = W1[t]; sW[t + 128] = W1[t + 128];
    if (t < 64) sb[t] = b1[t];
    __syncthreads();
    int i = blockIdx.x * 128 + t;
    if (i >= n) return;
    const float4* __restrict__ xs = (const float4*)g_xs;
    float4 a = xs[i];   // self term (already dinv-scaled)
    int b = g_off[i], e = b + g_cnt[i];
    int j = b;
    for (; j + 3 < e; j += 4) {
        int s0 = g_srcs[j],     s1 = g_srcs[j + 1];
        int s2 = g_srcs[j + 2], s3 = g_srcs[j + 3];
        float4 v0 = __ldg(xs + s0), v1 = __ldg(xs + s1);
        float4 v2 = __ldg(xs + s2), v3 = __ldg(xs + s3);
        a.x += (v0.x + v1.x) + (v2.x + v3.x);
        a.y += (v0.y + v1.y) + (v2.y + v3.y);
        a.z += (v0.z + v1.z) + (v2.z + v3.z);
        a.w += (v0.w + v1.w) + (v2.w + v3.w);
    }
    for (; j < e; j++) {
        float4 v = __ldg(xs + g_srcs[j]);
        a.x += v.x; a.y += v.y; a.z += v.z; a.w += v.w;
    }
    float dn = g_dinv[i];
    a.x *= dn; a.y *= dn; a.z *= dn; a.w *= dn;

    uint4* yo = (uint4*)(g_y1h + i * 64);
    #pragma unroll
    for (int fg = 0; fg < 8; fg++) {
        uint4 st;
        unsigned* sp = (unsigned*)&st;
        #pragma unroll
        for (int p = 0; p < 4; p++) {
            int f = fg * 8 + p * 2;
            float v0 = fmaf(a.x, sW[f],     fmaf(a.y, sW[64 + f],     fmaf(a.z, sW[128 + f],     a.w * sW[192 + f])))     + sb[f];
            float v1 = fmaf(a.x, sW[f + 1], fmaf(a.y, sW[64 + f + 1], fmaf(a.z, sW[128 + f + 1], a.w * sW[192 + f + 1]))) + sb[f + 1];
            __half2 h = __floats2half2_rn(fmaxf(v0, 0.0f) * dn, fmaxf(v1, 0.0f) * dn);
            sp[p] = *(unsigned*)&h;
        }
        yo[fg] = st;
    }
}

// ---------------- fused layer 2: gather + GEMM + relu + mean-pool -----------------
// Persistent: W2 loaded once per block; tiles of 64 nodes via grid-stride.
// smem sA layout: row = feature-pair k2 (32 rows), row content = 64 nodes x float2,
// row stride 132 words (16B-aligned rows, conflict-light STS.64 writes).
#define MB 64
#define ROWW 132
__global__ __launch_bounds__(256, 3)
void k_l2fused(const float* __restrict__ W2, const float* __restrict__ b2,
               const void* __restrict__ batch, int n, int nTiles) {
    __shared__ float sW[64 * 128];     // 32 KB
    __shared__ float sA[32 * ROWW];    // 16.5 KB
    __shared__ int   sB[MB];
    int t = threadIdx.x;  // 256
    int wid = t >> 5, lane = t & 31;
    int is64 = g_is64;
    for (int i = t; i < 64 * 128; i += 256) sW[i] = W2[i];

    const __half2* __restrict__ y1 = (const __half2*)g_y1h;
    int tx = t & 31;   // feature group: features 4tx .. 4tx+3
    int ty = t >> 5;   // node group:    nodes ty*8 .. ty*8+7 (local)
    float bias0 = b2[tx * 4], bias1 = b2[tx * 4 + 1];
    float bias2 = b2[tx * 4 + 2], bias3 = b2[tx * 4 + 3];

    for (int tile = blockIdx.x; tile < nTiles; tile += gridDim.x) {
        int base = tile * MB;
        if (t < MB) {
            int nt = base + t;
            sB[t] = (nt < n) ? ld_idx(batch, nt, is64) : -1;
        }
        // ---- gather phase: warp 'wid' handles nodes base+wid*8 .. +7;
        //      thread 'lane' owns feature pair (2*lane, 2*lane+1)
        #pragma unroll 1
        for (int q = 0; q < 8; q++) {
            int node = base + wid * 8 + q;
            float2 acc; acc.x = 0.0f; acc.y = 0.0f;
            if (node < n) {
                acc = __half22float2(y1[(node << 5) + lane]);   // self (pre-scaled)
                int b = g_off[node], e = b + g_cnt[node];
                int j = b;
                for (; j + 3 < e; j += 4) {
                    int s0 = g_srcs[j],     s1 = g_srcs[j + 1];
                    int s2 = g_srcs[j + 2], s3 = g_srcs[j + 3];
                    float2 f0 = __half22float2(__ldg(y1 + (s0 << 5) + lane));
                    float2 f1 = __half22float2(__ldg(y1 + (s1 << 5) + lane));
                    float2 f2 = __half22float2(__ldg(y1 + (s2 << 5) + lane));
                    float2 f3 = __half22float2(__ldg(y1 + (s3 << 5) + lane));
                    acc.x += (f0.x + f1.x) + (f2.x + f3.x);
                    acc.y += (f0.y + f1.y) + (f2.y + f3.y);
                }
                for (; j < e; j++) {
                    float2 f = __half22float2(__ldg(y1 + (g_srcs[j] << 5) + lane));
                    acc.x += f.x; acc.y += f.y;
                }
                float dn = g_dinv[node];
                acc.x *= dn; acc.y *= dn;
            }
            *(float2*)&sA[lane * ROWW + 2 * (wid * 8 + q)] = acc;
        }
        __syncthreads();

        // ---- GEMM phase: thread tile 8 nodes x 4 features, f32x2 packed FMA
        unsigned long long accp[8][2];
        #pragma unroll
        for (int q = 0; q < 8; q++) { accp[q][0] = 0ull; accp[q][1] = 0ull; }

        #pragma unroll 2
        for (int k2 = 0; k2 < 32; k2++) {
            const float* rw = &sW[(2 * k2) * 128 + tx * 4];
            float4 wv0 = *(const float4*)rw;            // weights for feature row k=2k2
            float4 wv1 = *(const float4*)(rw + 128);    // k=2k2+1
            ulonglong2 wp0 = *reinterpret_cast<ulonglong2*>(&wv0);
            ulonglong2 wp1 = *reinterpret_cast<ulonglong2*>(&wv1);
            const float* ra = &sA[k2 * ROWW + ty * 16];
            #pragma unroll
            for (int pj = 0; pj < 4; pj++) {
                float4 ap = *(const float4*)(ra + pj * 4);  // nodes 2pj, 2pj+1: (even,odd) each
                unsigned long long ae0, ao0, ae1, ao1;
                asm("mov.b64 %0, {%1, %1};" : "=l"(ae0) : "f"(ap.x));
                asm("mov.b64 %0, {%1, %1};" : "=l"(ao0) : "f"(ap.y));
                asm("mov.b64 %0, {%1, %1};" : "=l"(ae1) : "f"(ap.z));
                asm("mov.b64 %0, {%1, %1};" : "=l"(ao1) : "f"(ap.w));
                int q0 = pj * 2, q1 = pj * 2 + 1;
                asm("fma.rn.f32x2 %0, %1, %2, %0;" : "+l"(accp[q0][0]) : "l"(ae0), "l"(wp0.x));
                asm("fma.rn.f32x2 %0, %1, %2, %0;" : "+l"(accp[q0][1]) : "l"(ae0), "l"(wp0.y));
                asm("fma.rn.f32x2 %0, %1, %2, %0;" : "+l"(accp[q0][0]) : "l"(ao0), "l"(wp1.x));
                asm("fma.rn.f32x2 %0, %1, %2, %0;" : "+l"(accp[q0][1]) : "l"(ao0), "l"(wp1.y));
                asm("fma.rn.f32x2 %0, %1, %2, %0;" : "+l"(accp[q1][0]) : "l"(ae1), "l"(wp0.x));
                asm("fma.rn.f32x2 %0, %1, %2, %0;" : "+l"(accp[q1][1]) : "l"(ae1), "l"(wp0.y));
                asm("fma.rn.f32x2 %0, %1, %2, %0;" : "+l"(accp[q1][0]) : "l"(ao1), "l"(wp1.x));
                asm("fma.rn.f32x2 %0, %1, %2, %0;" : "+l"(accp[q1][1]) : "l"(ao1), "l"(wp1.y));
            }
        }

        // unpack + relu
        float y[8][4];
        #pragma unroll
        for (int q = 0; q < 8; q++) {
            float l0, h0, l1, h1;
            asm("mov.b64 {%0, %1}, %2;" : "=f"(l0), "=f"(h0) : "l"(accp[q][0]));
            asm("mov.b64 {%0, %1}, %2;" : "=f"(l1), "=f"(h1) : "l"(accp[q][1]));
            y[q][0] = fmaxf(l0 + bias0, 0.0f);
            y[q][1] = fmaxf(h0 + bias1, 0.0f);
            y[q][2] = fmaxf(l1 + bias2, 0.0f);
            y[q][3] = fmaxf(h1 + bias3, 0.0f);
        }

        // run-length pooled atomics over this thread's 8 (sorted-batch) nodes
        int cur = -1;
        float run0 = 0, run1 = 0, run2 = 0, run3 = 0;
        #pragma unroll
        for (int q = 0; q < 8; q++) {
            int g = sB[ty * 8 + q];
            if (g != cur) {
                if (cur >= 0) {
                    float* p = &g_pool[cur * 128 + tx * 4];
                    atomicAdd(p, run0); atomicAdd(p + 1, run1);
                    atomicAdd(p + 2, run2); atomicAdd(p + 3, run3);
                }
                cur = g; run0 = y[q][0]; run1 = y[q][1]; run2 = y[q][2]; run3 = y[q][3];
            } else {
                run0 += y[q][0]; run1 += y[q][1]; run2 += y[q][2]; run3 += y[q][3];
            }
        }
        if (cur >= 0) {
            float* p = &g_pool[cur * 128 + tx * 4];
            atomicAdd(p, run0); atomicAdd(p + 1, run1);
            atomicAdd(p + 2, run2); atomicAdd(p + 3, run3);
        }

        if (t == 0) {
            int rc = 0, cg = -1;
            for (int q = 0; q < MB; q++) {
                int g = sB[q];
                if (g != cg) {
                    if (cg >= 0) atomicAdd(&g_gcnt[cg], rc);
                    cg = g; rc = (g >= 0) ? 1 : 0;
                } else if (g >= 0) rc++;
            }
            if (cg >= 0) atomicAdd(&g_gcnt[cg], rc);
        }
        __syncthreads();   // protect sA/sB before next tile refill
    }
}

// ---------------- head: mean, fc1+relu, fc2 --------------------------------------
__global__ void k_head(const float* __restrict__ fc1W, const float* __restrict__ fc1b,
                       const float* __restrict__ fc2W, const float* __restrict__ fc2b,
                       float* __restrict__ out) {
    int g = blockIdx.x;
    int t = threadIdx.x;  // 128
    __shared__ float sv[128];
    __shared__ float red[64];
    float denom = fmaxf((float)g_gcnt[g], 1.0f);
    sv[t] = g_pool[g * 128 + t] / denom;
    __syncthreads();
    if (t < 64) {
        float a = fc1b[t];
        #pragma unroll 8
        for (int k = 0; k < 128; k++) a = fmaf(sv[k], fc1W[k * 64 + t], a);
        red[t] = fmaxf(a, 0.0f) * fc2W[t];
    }
    __syncthreads();
    if (t < 32) {
        float v = red[t] + red[t + 32];
        #pragma unroll
        for (int o = 16; o > 0; o >>= 1) v += __shfl_down_sync(0xffffffffu, v, o);
        if (t == 0) out[g] = v + fc2b[0];
    }
}

// ---------------- launch ----------------------------------------------------------
extern "C" void kernel_launch(void* const* d_in, const int* in_sizes, int n_in,
                              void* d_out, int out_size) {
    const float* x     = (const float*)d_in[0];
    const void*  ei    = d_in[1];
    const void*  batch = d_in[2];
    const float* W1    = (const float*)d_in[3];
    const float* b1    = (const float*)d_in[4];
    const float* W2    = (const float*)d_in[5];
    const float* b2    = (const float*)d_in[6];
    const float* fc1W  = (const float*)d_in[7];
    const float* fc1b  = (const float*)d_in[8];
    const float* fc2W  = (const float*)d_in[9];
    const float* fc2b  = (const float*)d_in[10];
    float* out = (float*)d_out;

    int N = in_sizes[0] / 4;   // 100000
    int E = in_sizes[1] / 2;   // 1600000

    k_detect<<<1, 32>>>((const unsigned int*)ei);

    int zmax = NG * 128;  // 131072 > NN
    k_zero<<<(zmax + 255) / 256, 256>>>();

    k_count<<<(E + 511) / 512, 512>>>(ei, E);

    int nb = (N + SCAN_B - 1) / SCAN_B;   // 98
    k_scan1<<<nb, SCAN_B>>>(N);
    k_scan2<<<1, 128>>>(nb);
    k_scan3<<<nb, SCAN_B>>>(x, N);

    k_fill<<<(E + 511) / 512, 512>>>(ei, E);

    k_l1<<<(N + 127) / 128, 128>>>(W1, b1, N);

    int nTiles = (N + MB - 1) / MB;        // 1563
    k_l2fused<<<444, 256>>>(W2, b2, batch, N, nTiles);

    k_head<<<NG, 128>>>(fc1W, fc1b, fc2W, fc2b, out);
}

// round 6
// speedup vs baseline: 1.0867x; 1.0867x over previous
#include <cuda_runtime.h>
#include <cuda_fp16.h>

#define NN 100000
#define NE 1600000
#define NG 1024
#define SCAN_B 1024

// ---------------- scratch (static __device__ — no allocation allowed) ----------
__device__ int    g_cnt[NN];        // incoming-edge count per node (excl. self loop)
__device__ int    g_off[NN];        // CSR exclusive offsets
__device__ int    g_fill[NN];       // bucket cursors
__device__ float  g_dinv[NN];       // 1/sqrt(deg) (deg incl. self loop)
__device__ int    g_bsum[128];      // per-tile scan partials (raw tile totals)
__device__ int    g_srcs[NE];       // CSR src ids (sorted by dst)
__device__ float  g_xs[NN * 4];     // dinv-prescaled input features
__device__ __half g_y1h[NN * 64];   // dinv * relu(a1 @ W1 + b1)  (layer-2 pre-scaled)
__device__ float  g_a2[NN * 64];    // layer-2 pre-projection aggregate
__device__ float  g_pool[NG * 128]; // graph-pooled sums
__device__ int    g_gcnt[NG];       // nodes per graph
__device__ int    g_is64;           // index dtype flag

// ---------------- index dtype handling -----------------------------------------
__device__ __forceinline__ int ld_idx(const void* p, long long i, int is64) {
    return is64 ? (int)((const long long*)p)[i] : ((const int*)p)[i];
}

// ---------------- init + dtype detect --------------------------------------------
__global__ void k_zero(const unsigned int* w) {
    int i = blockIdx.x * blockDim.x + threadIdx.x;
    if (i == 0) {
        int is64 = 1;
        #pragma unroll 1
        for (int k = 0; k < 256; k++) {
            if (w[2 * k + 1] != 0u) { is64 = 0; break; }
        }
        g_is64 = is64;
    }
    if (i < NN) { g_cnt[i] = 0; g_fill[i] = 0; }
    if (i < NG * 128) g_pool[i] = 0.0f;
    if (i < NG) g_gcnt[i] = 0;
}

// ---------------- CSR build -----------------------------------------------------
__global__ void k_count(const void* ei, int E) {
    int e = blockIdx.x * blockDim.x + threadIdx.x;
    if (e < E) {
        int is64 = g_is64;
        int d = ld_idx(ei, (long long)E + e, is64);
        atomicAdd(&g_cnt[d], 1);
    }
}

// grid-wide exclusive scan, phase 1: per-tile warp-shuffle scan + tile sums
__global__ void k_scan1(int n) {
    __shared__ int swarp[32];
    int t = threadIdx.x;
    int i = blockIdx.x * SCAN_B + t;
    int lane = t & 31, wid = t >> 5;
    int v = (i < n) ? g_cnt[i] : 0;
    int s = v;
    #pragma unroll
    for (int o = 1; o < 32; o <<= 1) {
        int u = __shfl_up_sync(0xffffffffu, s, o);
        if (lane >= o) s += u;
    }
    if (lane == 31) swarp[wid] = s;
    __syncthreads();
    if (wid == 0) {
        int ws = swarp[lane];
        #pragma unroll
        for (int o = 1; o < 32; o <<= 1) {
            int u = __shfl_up_sync(0xffffffffu, ws, o);
            if (lane >= o) ws += u;
        }
        swarp[lane] = ws;
    }
    __syncthreads();
    int incl = s + (wid > 0 ? swarp[wid - 1] : 0);
    if (i < n) g_off[i] = incl - v;   // exclusive within tile
    if (t == SCAN_B - 1) g_bsum[blockIdx.x] = incl;  // tile total
}

// phase 2 (fused): each block reduces tile totals before it; add offsets; dinv; prescale x
__global__ void k_scan3(const float* __restrict__ x, int n) {
    __shared__ int s_add;
    int t = threadIdx.x;
    if (t < 32) {
        int a = 0;
        for (int j = t; j < blockIdx.x; j += 32) a += g_bsum[j];
        #pragma unroll
        for (int o = 16; o > 0; o >>= 1) a += __shfl_down_sync(0xffffffffu, a, o);
        if (t == 0) s_add = a;
    }
    __syncthreads();
    int i = blockIdx.x * SCAN_B + t;
    if (i < n) {
        g_off[i] += s_add;
        float dn = rsqrtf((float)(g_cnt[i] + 1));   // +1 = self loop
        g_dinv[i] = dn;
        float4 xi = ((const float4*)x)[i];
        float4 r; r.x = dn * xi.x; r.y = dn * xi.y; r.z = dn * xi.z; r.w = dn * xi.w;
        ((float4*)g_xs)[i] = r;
    }
}

__global__ void k_fill(const void* ei, int E) {
    int e = blockIdx.x * blockDim.x + threadIdx.x;
    if (e < E) {
        int is64 = g_is64;
        int s = ld_idx(ei, e, is64);
        int d = ld_idx(ei, (long long)E + e, is64);
        int slot = g_off[d] + atomicAdd(&g_fill[d], 1);
        g_srcs[slot] = s;
    }
}

// ---------------- fused layer 1: gather-sum (4-dim) + W1 projection + relu -------
__global__ void k_l1(const float* __restrict__ W1, const float* __restrict__ b1, int n) {
    __shared__ float sW[256];
    __shared__ float sb[64];
    int t = threadIdx.x;  // 128
    sW[t] = W1[t]; sW[t + 128] = W1[t + 128];
    if (t < 64) sb[t] = b1[t];
    __syncthreads();
    int i = blockIdx.x * 128 + t;
    if (i >= n) return;
    const float4* __restrict__ xs = (const float4*)g_xs;
    float4 a = xs[i];   // self term (already dinv-scaled)
    int b = g_off[i], e = b + g_cnt[i];
    int j = b;
    for (; j + 3 < e; j += 4) {
        int s0 = g_srcs[j],     s1 = g_srcs[j + 1];
        int s2 = g_srcs[j + 2], s3 = g_srcs[j + 3];
        float4 v0 = __ldg(xs + s0), v1 = __ldg(xs + s1);
        float4 v2 = __ldg(xs + s2), v3 = __ldg(xs + s3);
        a.x += (v0.x + v1.x) + (v2.x + v3.x);
        a.y += (v0.y + v1.y) + (v2.y + v3.y);
        a.z += (v0.z + v1.z) + (v2.z + v3.z);
        a.w += (v0.w + v1.w) + (v2.w + v3.w);
    }
    for (; j < e; j++) {
        float4 v = __ldg(xs + g_srcs[j]);
        a.x += v.x; a.y += v.y; a.z += v.z; a.w += v.w;
    }
    float dn = g_dinv[i];
    a.x *= dn; a.y *= dn; a.z *= dn; a.w *= dn;

    uint4* yo = (uint4*)(g_y1h + i * 64);
    #pragma unroll
    for (int fg = 0; fg < 8; fg++) {
        uint4 st;
        unsigned* sp = (unsigned*)&st;
        #pragma unroll
        for (int p = 0; p < 4; p++) {
            int f = fg * 8 + p * 2;
            float v0 = fmaf(a.x, sW[f],     fmaf(a.y, sW[64 + f],     fmaf(a.z, sW[128 + f],     a.w * sW[192 + f])))     + sb[f];
            float v1 = fmaf(a.x, sW[f + 1], fmaf(a.y, sW[64 + f + 1], fmaf(a.z, sW[128 + f + 1], a.w * sW[192 + f + 1]))) + sb[f + 1];
            __half2 h = __floats2half2_rn(fmaxf(v0, 0.0f) * dn, fmaxf(v1, 0.0f) * dn);
            sp[p] = *(unsigned*)&h;
        }
        yo[fg] = st;
    }
}

// ---------------- layer 2: unweighted gather-sum in 64-dim fp16 space ------------
// blockDim (32,16): 32 threads per node (half2 each = one 128B line/edge); 16 nodes/block
__global__ void k_agg2(int n) {
    int node = blockIdx.x * 16 + threadIdx.y;
    if (node >= n) return;
    int t = threadIdx.x;   // 0..31
    const __half2* __restrict__ y1 = (const __half2*)g_y1h;
    float2 acc = __half22float2(y1[(node << 5) + t]);   // self term (pre-scaled)
    int b = g_off[node], e = b + g_cnt[node];
    int j = b;
    for (; j + 3 < e; j += 4) {
        int s0 = g_srcs[j],     s1 = g_srcs[j + 1];
        int s2 = g_srcs[j + 2], s3 = g_srcs[j + 3];
        float2 f0 = __half22float2(__ldg(y1 + (s0 << 5) + t));
        float2 f1 = __half22float2(__ldg(y1 + (s1 << 5) + t));
        float2 f2 = __half22float2(__ldg(y1 + (s2 << 5) + t));
        float2 f3 = __half22float2(__ldg(y1 + (s3 << 5) + t));
        acc.x += (f0.x + f1.x) + (f2.x + f3.x);
        acc.y += (f0.y + f1.y) + (f2.y + f3.y);
    }
    for (; j < e; j++) {
        float2 f = __half22float2(__ldg(y1 + (g_srcs[j] << 5) + t));
        acc.x += f.x; acc.y += f.y;
    }
    float dn = g_dinv[node];
    acc.x *= dn; acc.y *= dn;
    ((float2*)g_a2)[(node << 5) + t] = acc;
}

// ---------------- y2 = relu(a2 @ W2 + b2) fused with graph mean-pool sums --------
// 256 threads, 64 nodes/block. Thread tile: 8 nodes x 4 features, f32x2 packed FMA.
#define MB 64
#define NQ 8
#define AT_STRIDE 68
__global__ void k_gemm2pool(const float* __restrict__ W2, const float* __restrict__ b2,
                            const void* __restrict__ batch, int n) {
    __shared__ float sW[64 * 128];          // 32 KB
    __shared__ float sAT[64 * AT_STRIDE];   // 17 KB  (transposed a2: [k][node])
    __shared__ int   sB[MB];
    int t = threadIdx.x;  // 256
    for (int i = t; i < 64 * 128; i += 256) sW[i] = W2[i];
    int base = blockIdx.x * MB;
    for (int i = t; i < MB * 64; i += 256) {
        int nl = i >> 6, k = i & 63;
        int nt = base + nl;
        sAT[k * AT_STRIDE + nl] = (nt < n) ? g_a2[nt * 64 + k] : 0.0f;
    }
    if (t < MB) {
        int nt = base + t;
        sB[t] = (nt < n) ? ld_idx(batch, nt, g_is64) : -1;
    }
    __syncthreads();

    int tx = t & 31;   // feature group: features tx*4 .. tx*4+3
    int ty = t >> 5;   // node group:    nodes ty*8 .. ty*8+7 (local)

    unsigned long long accp[NQ][2];   // [node q][feature pair]
    #pragma unroll
    for (int q = 0; q < NQ; q++) { accp[q][0] = 0ull; accp[q][1] = 0ull; }

    #pragma unroll 2
    for (int k = 0; k < 64; k++) {
        float4 wv = *(const float4*)&sW[k * 128 + tx * 4];
        ulonglong2 wp = *reinterpret_cast<ulonglong2*>(&wv);   // {w0,w1},{w2,w3}
        float4 av0 = *(const float4*)&sAT[k * AT_STRIDE + ty * 8];
        float4 av1 = *(const float4*)&sAT[k * AT_STRIDE + ty * 8 + 4];
        float aq[NQ] = {av0.x, av0.y, av0.z, av0.w, av1.x, av1.y, av1.z, av1.w};
        #pragma unroll
        for (int q = 0; q < NQ; q++) {
            unsigned long long ad;
            asm("mov.b64 %0, {%1, %1};" : "=l"(ad) : "f"(aq[q]));
            asm("fma.rn.f32x2 %0, %1, %2, %0;" : "+l"(accp[q][0]) : "l"(ad), "l"(wp.x));
            asm("fma.rn.f32x2 %0, %1, %2, %0;" : "+l"(accp[q][1]) : "l"(ad), "l"(wp.y));
        }
    }

    float bias0 = b2[tx * 4], bias1 = b2[tx * 4 + 1];
    float bias2 = b2[tx * 4 + 2], bias3 = b2[tx * 4 + 3];

    // unpack + relu
    float y[NQ][4];
    #pragma unroll
    for (int q = 0; q < NQ; q++) {
        float l0, h0, l1, h1;
        asm("mov.b64 {%0, %1}, %2;" : "=f"(l0), "=f"(h0) : "l"(accp[q][0]));
        asm("mov.b64 {%0, %1}, %2;" : "=f"(l1), "=f"(h1) : "l"(accp[q][1]));
        y[q][0] = fmaxf(l0 + bias0, 0.0f);
        y[q][1] = fmaxf(h0 + bias1, 0.0f);
        y[q][2] = fmaxf(l1 + bias2, 0.0f);
        y[q][3] = fmaxf(h1 + bias3, 0.0f);
    }

    // run-length pooled atomics over this thread's NQ (sorted-batch) nodes
    int cur = -1;
    float run0 = 0, run1 = 0, run2 = 0, run3 = 0;
    #pragma unroll
    for (int q = 0; q < NQ; q++) {
        int g = sB[ty * NQ + q];
        if (g != cur) {
            if (cur >= 0) {
                float* p = &g_pool[cur * 128 + tx * 4];
                atomicAdd(p, run0); atomicAdd(p + 1, run1);
                atomicAdd(p + 2, run2); atomicAdd(p + 3, run3);
            }
            cur = g; run0 = y[q][0]; run1 = y[q][1]; run2 = y[q][2]; run3 = y[q][3];
        } else {
            run0 += y[q][0]; run1 += y[q][1]; run2 += y[q][2]; run3 += y[q][3];
        }
    }
    if (cur >= 0) {
        float* p = &g_pool[cur * 128 + tx * 4];
        atomicAdd(p, run0); atomicAdd(p + 1, run1);
        atomicAdd(p + 2, run2); atomicAdd(p + 3, run3);
    }

    if (t == 0) {
        int rc = 0, cg = -1;
        for (int q = 0; q < MB; q++) {
            int g = sB[q];
            if (g != cg) {
                if (cg >= 0) atomicAdd(&g_gcnt[cg], rc);
                cg = g; rc = (g >= 0) ? 1 : 0;
            } else if (g >= 0) rc++;
        }
        if (cg >= 0) atomicAdd(&g_gcnt[cg], rc);
    }
}

// ---------------- head: mean, fc1+relu, fc2 --------------------------------------
__global__ void k_head(const float* __restrict__ fc1W, const float* __restrict__ fc1b,
                       const float* __restrict__ fc2W, const float* __restrict__ fc2b,
                       float* __restrict__ out) {
    int g = blockIdx.x;
    int t = threadIdx.x;  // 128
    __shared__ float sv[128];
    __shared__ float red[64];
    float denom = fmaxf((float)g_gcnt[g], 1.0f);
    sv[t] = g_pool[g * 128 + t] / denom;
    __syncthreads();
    if (t < 64) {
        float a = fc1b[t];
        #pragma unroll 8
        for (int k = 0; k < 128; k++) a = fmaf(sv[k], fc1W[k * 64 + t], a);
        red[t] = fmaxf(a, 0.0f) * fc2W[t];
    }
    __syncthreads();
    if (t < 32) {
        float v = red[t] + red[t + 32];
        #pragma unroll
        for (int o = 16; o > 0; o >>= 1) v += __shfl_down_sync(0xffffffffu, v, o);
        if (t == 0) out[g] = v + fc2b[0];
    }
}

// ---------------- launch ----------------------------------------------------------
extern "C" void kernel_launch(void* const* d_in, const int* in_sizes, int n_in,
                              void* d_out, int out_size) {
    const float* x     = (const float*)d_in[0];
    const void*  ei    = d_in[1];
    const void*  batch = d_in[2];
    const float* W1    = (const float*)d_in[3];
    const float* b1    = (const float*)d_in[4];
    const float* W2    = (const float*)d_in[5];
    const float* b2    = (const float*)d_in[6];
    const float* fc1W  = (const float*)d_in[7];
    const float* fc1b  = (const float*)d_in[8];
    const float* fc2W  = (const float*)d_in[9];
    const float* fc2b  = (const float*)d_in[10];
    float* out = (float*)d_out;

    int N = in_sizes[0] / 4;   // 100000
    int E = in_sizes[1] / 2;   // 1600000

    int zmax = NG * 128;  // 131072 > NN
    k_zero<<<(zmax + 255) / 256, 256>>>((const unsigned int*)ei);

    k_count<<<(E + 511) / 512, 512>>>(ei, E);

    int nb = (N + SCAN_B - 1) / SCAN_B;   // 98
    k_scan1<<<nb, SCAN_B>>>(N);
    k_scan3<<<nb, SCAN_B>>>(x, N);

    k_fill<<<(E + 511) / 512, 512>>>(ei, E);

    k_l1<<<(N + 127) / 128, 128>>>(W1, b1, N);

    dim3 bt2(32, 16);
    k_agg2<<<(N + 15) / 16, bt2>>>(N);

    k_gemm2pool<<<(N + MB - 1) / MB, 256>>>(W2, b2, batch, N);

    k_head<<<NG, 128>>>(fc1W, fc1b, fc2W, fc2b, out);
}

// round 7
// speedup vs baseline: 1.3307x; 1.2245x over previous
#include <cuda_runtime.h>
#include <cuda_fp16.h>

#define NN 100000
#define NE 1600000
#define NG 1024
#define SCAN_B 1024

// ---------------- scratch (static __device__ — no allocation allowed) ----------
__device__ int    g_cnt[NN];        // incoming-edge count per node (excl. self loop)
__device__ int    g_off[NN];        // CSR exclusive offsets
__device__ int    g_fill[NN];       // bucket cursors
__device__ float  g_dinv[NN];       // 1/sqrt(deg) (deg incl. self loop)
__device__ int    g_bsum[128];      // per-tile scan partials (raw tile totals)
__device__ int    g_srcs[NE];       // CSR src ids (sorted by dst)
__device__ float  g_xs[NN * 4];     // dinv-prescaled input features
__device__ __half g_y1h[NN * 64];   // dinv * relu(a1 @ W1 + b1)  (layer-2 pre-scaled)
__device__ __half g_a2h[NN * 64];   // layer-2 pre-projection aggregate (fp16)
__device__ float  g_pool[NG * 128]; // graph-pooled sums
__device__ int    g_gcnt[NG];       // nodes per graph
__device__ int    g_is64;           // index dtype flag

// ---------------- index dtype handling -----------------------------------------
__device__ __forceinline__ int ld_idx(const void* p, long long i, int is64) {
    return is64 ? (int)((const long long*)p)[i] : ((const int*)p)[i];
}

// ---------------- init + dtype detect --------------------------------------------
__global__ void k_zero(const unsigned int* w) {
    int i = blockIdx.x * blockDim.x + threadIdx.x;
    if (i == 0) {
        int is64 = 1;
        #pragma unroll 1
        for (int k = 0; k < 256; k++) {
            if (w[2 * k + 1] != 0u) { is64 = 0; break; }
        }
        g_is64 = is64;
    }
    if (i < NN) { g_cnt[i] = 0; g_fill[i] = 0; }
    if (i < NG * 128) g_pool[i] = 0.0f;
    if (i < NG) g_gcnt[i] = 0;
}

// ---------------- CSR build -----------------------------------------------------
__global__ void k_count(const void* ei, int E) {
    int e = blockIdx.x * blockDim.x + threadIdx.x;
    if (e < E) {
        int is64 = g_is64;
        int d = ld_idx(ei, (long long)E + e, is64);
        atomicAdd(&g_cnt[d], 1);
    }
}

// grid-wide exclusive scan, phase 1: per-tile warp-shuffle scan + tile sums
__global__ void k_scan1(int n) {
    __shared__ int swarp[32];
    int t = threadIdx.x;
    int i = blockIdx.x * SCAN_B + t;
    int lane = t & 31, wid = t >> 5;
    int v = (i < n) ? g_cnt[i] : 0;
    int s = v;
    #pragma unroll
    for (int o = 1; o < 32; o <<= 1) {
        int u = __shfl_up_sync(0xffffffffu, s, o);
        if (lane >= o) s += u;
    }
    if (lane == 31) swarp[wid] = s;
    __syncthreads();
    if (wid == 0) {
        int ws = swarp[lane];
        #pragma unroll
        for (int o = 1; o < 32; o <<= 1) {
            int u = __shfl_up_sync(0xffffffffu, ws, o);
            if (lane >= o) ws += u;
        }
        swarp[lane] = ws;
    }
    __syncthreads();
    int incl = s + (wid > 0 ? swarp[wid - 1] : 0);
    if (i < n) g_off[i] = incl - v;   // exclusive within tile
    if (t == SCAN_B - 1) g_bsum[blockIdx.x] = incl;  // tile total
}

// phase 2 (fused): each block reduces tile totals before it; add offsets; dinv; prescale x
__global__ void k_scan3(const float* __restrict__ x, int n) {
    __shared__ int s_add;
    int t = threadIdx.x;
    if (t < 32) {
        int a = 0;
        for (int j = t; j < blockIdx.x; j += 32) a += g_bsum[j];
        #pragma unroll
        for (int o = 16; o > 0; o >>= 1) a += __shfl_down_sync(0xffffffffu, a, o);
        if (t == 0) s_add = a;
    }
    __syncthreads();
    int i = blockIdx.x * SCAN_B + t;
    if (i < n) {
        g_off[i] += s_add;
        float dn = rsqrtf((float)(g_cnt[i] + 1));   // +1 = self loop
        g_dinv[i] = dn;
        float4 xi = ((const float4*)x)[i];
        float4 r; r.x = dn * xi.x; r.y = dn * xi.y; r.z = dn * xi.z; r.w = dn * xi.w;
        ((float4*)g_xs)[i] = r;
    }
}

__global__ void k_fill(const void* ei, int E) {
    int e = blockIdx.x * blockDim.x + threadIdx.x;
    if (e < E) {
        int is64 = g_is64;
        int s = ld_idx(ei, e, is64);
        int d = ld_idx(ei, (long long)E + e, is64);
        int slot = g_off[d] + atomicAdd(&g_fill[d], 1);
        g_srcs[slot] = s;
    }
}

// ---------------- fused layer 1: gather-sum (4-dim) + W1 projection + relu -------
__global__ void k_l1(const float* __restrict__ W1, const float* __restrict__ b1, int n) {
    __shared__ float sW[256];
    __shared__ float sb[64];
    int t = threadIdx.x;  // 128
    sW[t] = W1[t]; sW[t + 128] = W1[t + 128];
    if (t < 64) sb[t] = b1[t];
    __syncthreads();
    int i = blockIdx.x * 128 + t;
    if (i >= n) return;
    const float4* __restrict__ xs = (const float4*)g_xs;
    float4 a = xs[i];   // self term (already dinv-scaled)
    int b = g_off[i], e = b + g_cnt[i];
    int j = b;
    for (; j + 3 < e; j += 4) {
        int s0 = g_srcs[j],     s1 = g_srcs[j + 1];
        int s2 = g_srcs[j + 2], s3 = g_srcs[j + 3];
        float4 v0 = __ldg(xs + s0), v1 = __ldg(xs + s1);
        float4 v2 = __ldg(xs + s2), v3 = __ldg(xs + s3);
        a.x += (v0.x + v1.x) + (v2.x + v3.x);
        a.y += (v0.y + v1.y) + (v2.y + v3.y);
        a.z += (v0.z + v1.z) + (v2.z + v3.z);
        a.w += (v0.w + v1.w) + (v2.w + v3.w);
    }
    for (; j < e; j++) {
        float4 v = __ldg(xs + g_srcs[j]);
        a.x += v.x; a.y += v.y; a.z += v.z; a.w += v.w;
    }
    float dn = g_dinv[i];
    a.x *= dn; a.y *= dn; a.z *= dn; a.w *= dn;

    uint4* yo = (uint4*)(g_y1h + i * 64);
    #pragma unroll
    for (int fg = 0; fg < 8; fg++) {
        uint4 st;
        unsigned* sp = (unsigned*)&st;
        #pragma unroll
        for (int p = 0; p < 4; p++) {
            int f = fg * 8 + p * 2;
            float v0 = fmaf(a.x, sW[f],     fmaf(a.y, sW[64 + f],     fmaf(a.z, sW[128 + f],     a.w * sW[192 + f])))     + sb[f];
            float v1 = fmaf(a.x, sW[f + 1], fmaf(a.y, sW[64 + f + 1], fmaf(a.z, sW[128 + f + 1], a.w * sW[192 + f + 1]))) + sb[f + 1];
            __half2 h = __floats2half2_rn(fmaxf(v0, 0.0f) * dn, fmaxf(v1, 0.0f) * dn);
            sp[p] = *(unsigned*)&h;
        }
        yo[fg] = st;
    }
}

// ---------------- layer 2: unweighted gather-sum in 64-dim fp16 space ------------
__global__ void k_agg2(int n) {
    int node = blockIdx.x * 16 + threadIdx.y;
    if (node >= n) return;
    int t = threadIdx.x;   // 0..31
    const __half2* __restrict__ y1 = (const __half2*)g_y1h;
    float2 acc = __half22float2(y1[(node << 5) + t]);   // self term (pre-scaled)
    int b = g_off[node], e = b + g_cnt[node];
    int j = b;
    for (; j + 3 < e; j += 4) {
        int s0 = g_srcs[j],     s1 = g_srcs[j + 1];
        int s2 = g_srcs[j + 2], s3 = g_srcs[j + 3];
        float2 f0 = __half22float2(__ldg(y1 + (s0 << 5) + t));
        float2 f1 = __half22float2(__ldg(y1 + (s1 << 5) + t));
        float2 f2 = __half22float2(__ldg(y1 + (s2 << 5) + t));
        float2 f3 = __half22float2(__ldg(y1 + (s3 << 5) + t));
        acc.x += (f0.x + f1.x) + (f2.x + f3.x);
        acc.y += (f0.y + f1.y) + (f2.y + f3.y);
    }
    for (; j < e; j++) {
        float2 f = __half22float2(__ldg(y1 + (g_srcs[j] << 5) + t));
        acc.x += f.x; acc.y += f.y;
    }
    float dn = g_dinv[node];
    ((__half2*)g_a2h)[(node << 5) + t] = __floats2half2_rn(acc.x * dn, acc.y * dn);
}

// ---------------- y2 = relu(a2 @ W2 + b2) via HMMA, fused mean-pool --------------
// 256 threads = 8 warps; tile = 64 nodes x 128 features; K = 64.
// warp w: node-group ng = w>>1 (16 nodes), feature-half fh = w&1 (64 features).
// Fragments loaded with direct LDS per the PTX m16n8k16 fragment spec
// (pad-to-72 rows make every fragment load bank-conflict-free).
#define MB 64
#define APAD 72
#define CPAD 132
__global__ void k_gemm2pool(const float* __restrict__ W2, const float* __restrict__ b2,
                            const void* __restrict__ batch, int n, int nTiles) {
    __shared__ __align__(16) __half sW2T[128 * APAD];                 // 18432 B, persists
    __shared__ __align__(16) unsigned char sU[MB * CPAD * 2];        // union: sA / sC (16896 B)
    __shared__ int sB[MB];
    __half* sA = (__half*)sU;          // [64][APAD] fp16 a2 tile
    __half* sC = (__half*)sU;          // [64][CPAD] fp16 y2 staging (raw, pre-bias)
    int t = threadIdx.x;  // 256
    int lane = t & 31, w = t >> 5;
    int is64 = g_is64;

    // W2 [64,128] f32 -> sW2T [n][k] fp16 (once per block)
    for (int i = t; i < 64 * 128; i += 256) {
        int k = i >> 7, nn_ = i & 127;
        sW2T[nn_ * APAD + k] = __float2half(W2[i]);
    }

    int ng = w >> 1, fh = w & 1;
    int g = lane >> 2, tt = lane & 3;
    int tx = t & 31;     // pooling: features 4tx..4tx+3
    int ty = t >> 5;     // pooling: nodes 8ty..8ty+7
    float bias0 = b2[tx * 4], bias1 = b2[tx * 4 + 1];
    float bias2 = b2[tx * 4 + 2], bias3 = b2[tx * 4 + 3];
    __syncthreads();

    for (int tile = blockIdx.x; tile < nTiles; tile += gridDim.x) {
        int base = tile * MB;
        // ---- load a2 tile (fp16) + batch ids
        const unsigned* a2u = (const unsigned*)g_a2h;
        for (int i = t; i < MB * 32; i += 256) {
            int nl = i >> 5, c = i & 31;
            int nt = base + nl;
            unsigned v = (nt < n) ? a2u[nt * 32 + c] : 0u;
            *(unsigned*)&sA[nl * APAD + 2 * c] = v;
        }
        if (t < MB) {
            int nt = base + t;
            sB[t] = (nt < n) ? ld_idx(batch, nt, is64) : -1;
        }
        __syncthreads();

        // ---- HMMA: per warp M=16 (ng), N=64 (fh), K=64
        float acc[8][4];
        #pragma unroll
        for (int nt = 0; nt < 8; nt++)
            #pragma unroll
            for (int q = 0; q < 4; q++) acc[nt][q] = 0.0f;

        #pragma unroll
        for (int ks = 0; ks < 4; ks++) {
            int k0 = ks * 16 + 2 * tt;
            const __half* arow0 = &sA[(ng * 16 + g) * APAD + k0];
            const __half* arow1 = arow0 + 8 * APAD;
            unsigned a0 = *(const unsigned*)arow0;
            unsigned a1 = *(const unsigned*)arow1;
            unsigned a2_ = *(const unsigned*)(arow0 + 8);
            unsigned a3 = *(const unsigned*)(arow1 + 8);
            #pragma unroll
            for (int nt = 0; nt < 8; nt++) {
                const __half* brow = &sW2T[(fh * 64 + nt * 8 + g) * APAD + k0];
                unsigned b0 = *(const unsigned*)brow;
                unsigned b1 = *(const unsigned*)(brow + 8);
                asm volatile(
                    "mma.sync.aligned.m16n8k16.row.col.f32.f16.f16.f32 "
                    "{%0,%1,%2,%3}, {%4,%5,%6,%7}, {%8,%9}, {%0,%1,%2,%3};"
                    : "+f"(acc[nt][0]), "+f"(acc[nt][1]), "+f"(acc[nt][2]), "+f"(acc[nt][3])
                    : "r"(a0), "r"(a1), "r"(a2_), "r"(a3), "r"(b0), "r"(b1));
            }
        }
        __syncthreads();   // sA dead; safe to overwrite as sC

        // ---- stage raw C (fp16) to smem
        #pragma unroll
        for (int nt = 0; nt < 8; nt++) {
            int row = ng * 16 + g;
            int col = fh * 64 + nt * 8 + 2 * tt;
            __half2 lo = __floats2half2_rn(acc[nt][0], acc[nt][1]);
            __half2 hi = __floats2half2_rn(acc[nt][2], acc[nt][3]);
            *(__half2*)&sC[row * CPAD + col] = lo;
            *(__half2*)&sC[(row + 8) * CPAD + col] = hi;
        }
        __syncthreads();

        // ---- bias + relu + run-length pooled atomics (batch sorted)
        int cur = -1;
        float run0 = 0, run1 = 0, run2 = 0, run3 = 0;
        #pragma unroll
        for (int q = 0; q < 8; q++) {
            int nl = ty * 8 + q;
            int gb = sB[nl];
            float2 v01 = __half22float2(*(const __half2*)&sC[nl * CPAD + 4 * tx]);
            float2 v23 = __half22float2(*(const __half2*)&sC[nl * CPAD + 4 * tx + 2]);
            float y0 = (gb >= 0) ? fmaxf(v01.x + bias0, 0.0f) : 0.0f;
            float y1v = (gb >= 0) ? fmaxf(v01.y + bias1, 0.0f) : 0.0f;
            float y2v = (gb >= 0) ? fmaxf(v23.x + bias2, 0.0f) : 0.0f;
            float y3 = (gb >= 0) ? fmaxf(v23.y + bias3, 0.0f) : 0.0f;
            if (gb != cur) {
                if (cur >= 0) {
                    float* p = &g_pool[cur * 128 + tx * 4];
                    atomicAdd(p, run0); atomicAdd(p + 1, run1);
                    atomicAdd(p + 2, run2); atomicAdd(p + 3, run3);
                }
                cur = gb; run0 = y0; run1 = y1v; run2 = y2v; run3 = y3;
            } else {
                run0 += y0; run1 += y1v; run2 += y2v; run3 += y3;
            }
        }
        if (cur >= 0) {
            float* p = &g_pool[cur * 128 + tx * 4];
            atomicAdd(p, run0); atomicAdd(p + 1, run1);
            atomicAdd(p + 2, run2); atomicAdd(p + 3, run3);
        }

        if (t == 0) {
            int rc = 0, cg = -1;
            for (int q = 0; q < MB; q++) {
                int gb = sB[q];
                if (gb != cg) {
                    if (cg >= 0) atomicAdd(&g_gcnt[cg], rc);
                    cg = gb; rc = (gb >= 0) ? 1 : 0;
                } else if (gb >= 0) rc++;
            }
            if (cg >= 0) atomicAdd(&g_gcnt[cg], rc);
        }
        __syncthreads();   // protect sC/sB before next tile's sA fill
    }
}

// ---------------- head: mean, fc1+relu, fc2 --------------------------------------
__global__ void k_head(const float* __restrict__ fc1W, const float* __restrict__ fc1b,
                       const float* __restrict__ fc2W, const float* __restrict__ fc2b,
                       float* __restrict__ out) {
    int g = blockIdx.x;
    int t = threadIdx.x;  // 128
    __shared__ float sv[128];
    __shared__ float red[64];
    float denom = fmaxf((float)g_gcnt[g], 1.0f);
    sv[t] = g_pool[g * 128 + t] / denom;
    __syncthreads();
    if (t < 64) {
        float a = fc1b[t];
        #pragma unroll 8
        for (int k = 0; k < 128; k++) a = fmaf(sv[k], fc1W[k * 64 + t], a);
        red[t] = fmaxf(a, 0.0f) * fc2W[t];
    }
    __syncthreads();
    if (t < 32) {
        float v = red[t] + red[t + 32];
        #pragma unroll
        for (int o = 16; o > 0; o >>= 1) v += __shfl_down_sync(0xffffffffu, v, o);
        if (t == 0) out[g] = v + fc2b[0];
    }
}

// ---------------- launch ----------------------------------------------------------
extern "C" void kernel_launch(void* const* d_in, const int* in_sizes, int n_in,
                              void* d_out, int out_size) {
    const float* x     = (const float*)d_in[0];
    const void*  ei    = d_in[1];
    const void*  batch = d_in[2];
    const float* W1    = (const float*)d_in[3];
    const float* b1    = (const float*)d_in[4];
    const float* W2    = (const float*)d_in[5];
    const float* b2    = (const float*)d_in[6];
    const float* fc1W  = (const float*)d_in[7];
    const float* fc1b  = (const float*)d_in[8];
    const float* fc2W  = (const float*)d_in[9];
    const float* fc2b  = (const float*)d_in[10];
    float* out = (float*)d_out;

    int N = in_sizes[0] / 4;   // 100000
    int E = in_sizes[1] / 2;   // 1600000

    int zmax = NG * 128;  // 131072 > NN
    k_zero<<<(zmax + 255) / 256, 256>>>((const unsigned int*)ei);

    k_count<<<(E + 511) / 512, 512>>>(ei, E);

    int nb = (N + SCAN_B - 1) / SCAN_B;   // 98
    k_scan1<<<nb, SCAN_B>>>(N);
    k_scan3<<<nb, SCAN_B>>>(x, N);

    k_fill<<<(E + 511) / 512, 512>>>(ei, E);

    k_l1<<<(N + 127) / 128, 128>>>(W1, b1, N);

    dim3 bt2(32, 16);
    k_agg2<<<(N + 15) / 16, bt2>>>(N);

    int nTiles = (N + MB - 1) / MB;        // 1563
    k_gemm2pool<<<521, 256>>>(W2, b2, batch, N, nTiles);

    k_head<<<NG, 128>>>(fc1W, fc1b, fc2W, fc2b, out);
}